// round 2
// baseline (speedup 1.0000x reference)
#include <cuda_runtime.h>
#include <math.h>

#define B 4
#define N 512
#define HID 100      // real hidden size
#define HP 128       // padded hidden (uniform warps, power-of-2 addressing)
#define OUTF 6
#define I_TILE 8     // receivers per K2 block

// Scratch (static device arrays; no allocation anywhere)
__device__ float g_P[B * N * HP];          // P'_i[k] (receiver part + b1)
__device__ float g_Q[B * N * HP];          // Q_j[k]  (sender part)
__device__ float g_sumQ[B * HP];           // sum over j of Q_j[k]
__device__ float g_T[2 * B * N * HP];      // partial sums of |P_i+Q_j| (2 j-groups)

// ---------------------------------------------------------------------------
// K1: build P' and Q.  idx -> (bn, k).  k >= HID lanes write zeros (padding).
// ---------------------------------------------------------------------------
__global__ __launch_bounds__(256) void k1_build_PQ(
    const float* __restrict__ inp, const float* __restrict__ W1,
    const float* __restrict__ b1)
{
    int idx = blockIdx.x * blockDim.x + threadIdx.x;
    if (idx >= B * N * HP) return;
    int k  = idx & (HP - 1);
    int bn = idx >> 7;

    const float* e = inp + bn * 6;
    float y = e[0], x = e[1], tau = e[2], sig = e[3], c = e[4], d = e[5];

    float P = 0.f, Q = 0.f;
    if (k < HID) {
        float w0 = W1[0 * HID + k], w1 = W1[1 * HID + k];
        float w2 = W1[2 * HID + k], w3 = W1[3 * HID + k];
        float w4 = W1[4 * HID + k], w5 = W1[5 * HID + k];
        float w6 = W1[6 * HID + k], w7 = W1[7 * HID + k];
        float w8 = W1[8 * HID + k], w9 = W1[9 * HID + k];
        P = tau * w0 + sig * w1 + c * w2 + d * w3 + y * w8 + x * w9 + b1[k];
        Q = tau * w4 + sig * w5 + c * w6 + d * w7 - y * w8 - x * w9;
    }
    g_P[idx] = P;
    g_Q[idx] = Q;
}

// ---------------------------------------------------------------------------
// K1b: sumQ[b][k] = sum_j Q[b][j][k].  One block per b, 512 threads:
// thread = (jgroup 0..3, k 0..127); each sums 128 j's, shared-reduce 4 partials.
// ---------------------------------------------------------------------------
__global__ __launch_bounds__(512) void k1b_sumQ()
{
    int b = blockIdx.x;
    int t = threadIdx.x;
    int k = t & (HP - 1);
    int g = t >> 7;                 // 0..3
    const float* q = g_Q + (b * N + g * (N / 4)) * HP + k;

    float s0 = 0.f, s1 = 0.f, s2 = 0.f, s3 = 0.f;
    #pragma unroll 8
    for (int j = 0; j < N / 4; j += 4) {
        s0 += q[(j + 0) * HP];
        s1 += q[(j + 1) * HP];
        s2 += q[(j + 2) * HP];
        s3 += q[(j + 3) * HP];
    }
    __shared__ float sm[512];
    sm[t] = (s0 + s1) + (s2 + s3);
    __syncthreads();
    if (g == 0)
        g_sumQ[b * HP + k] = (sm[k] + sm[k + 128]) + (sm[k + 256] + sm[k + 384]);
}

// ---------------------------------------------------------------------------
// K2: the O(N^2) part.  T_partial[g][b][i][k] = sum_{j in group g} |P_i[k]+Q_j[k]|
// Block = (b, tile of 8 i's), 256 threads = 2 j-groups x 128 k-lanes.
// Per thread: 256 j iters x 8 i x 2 FADD.
// ---------------------------------------------------------------------------
__global__ __launch_bounds__(256) void k2_pair_abs_sum()
{
    int blk = blockIdx.x;               // 0..255
    int b   = blk >> 6;                 // 64 tiles per batch
    int i0  = (blk & 63) * I_TILE;
    int k   = threadIdx.x & (HP - 1);
    int g   = threadIdx.x >> 7;         // j-group: 0 or 1

    const float* Pp = g_P + (b * N + i0) * HP + k;
    float p[I_TILE];
    #pragma unroll
    for (int ii = 0; ii < I_TILE; ii++) p[ii] = Pp[ii * HP];

    float acc[I_TILE];
    #pragma unroll
    for (int ii = 0; ii < I_TILE; ii++) acc[ii] = 0.f;

    const float* q = g_Q + (b * N + g * (N / 2)) * HP + k;
    #pragma unroll 8
    for (int j = 0; j < N / 2; j++) {
        float qv = q[j * HP];
        #pragma unroll
        for (int ii = 0; ii < I_TILE; ii++) {
            float t = p[ii] + qv;
            acc[ii] += fabsf(t);
        }
    }

    float* outp = g_T + (((g * B + b) * N) + i0) * HP + k;
    #pragma unroll
    for (int ii = 0; ii < I_TILE; ii++) outp[ii * HP] = acc[ii];
}

// ---------------------------------------------------------------------------
// K3: per (b,i) epilogue.  S[k] = 0.55*((N-1)*P'_i[k] + sumQ[k] - Q_i[k])
//                               + 0.45*(T_i[k] - |P'_i[k]+Q_i[k]|)
// p_out[o] = sum_k W2[k][o]*S[k] + (N-1)*b2[o]; then final combine + softplus.
// ---------------------------------------------------------------------------
__device__ __forceinline__ float softplus_f(float v)
{
    return fmaxf(v, 0.f) + log1pf(expf(-fabsf(v)));
}

__global__ __launch_bounds__(128) void k3_epilogue(
    const float* __restrict__ inp, const float* __restrict__ W2,
    const float* __restrict__ b2, float* __restrict__ out)
{
    int bi = blockIdx.x;                // 0..2047
    int b  = bi >> 9;
    int i  = bi & (N - 1);
    int k  = threadIdx.x;               // 0..127

    int base = (b * N + i) * HP + k;
    float T  = g_T[base] + g_T[(B * N * HP) + base];
    float Pi = g_P[base];
    float Qi = g_Q[base];
    float sq = g_sumQ[b * HP + k];

    float S = 0.55f * ((float)(N - 1) * Pi + sq - Qi)
            + 0.45f * (T - fabsf(Pi + Qi));

    float par[OUTF];
    #pragma unroll
    for (int o = 0; o < OUTF; o++)
        par[o] = (k < HID) ? S * W2[k * OUTF + o] : 0.f;

    // warp butterfly reduce
    #pragma unroll
    for (int off = 16; off > 0; off >>= 1) {
        #pragma unroll
        for (int o = 0; o < OUTF; o++)
            par[o] += __shfl_down_sync(0xFFFFFFFFu, par[o], off);
    }
    __shared__ float sm[4][OUTF];
    if ((k & 31) == 0) {
        #pragma unroll
        for (int o = 0; o < OUTF; o++) sm[k >> 5][o] = par[o];
    }
    __syncthreads();
    if (k == 0) {
        float p[OUTF];
        #pragma unroll
        for (int o = 0; o < OUTF; o++)
            p[o] = (sm[0][o] + sm[1][o]) + (sm[2][o] + sm[3][o])
                 + (float)(N - 1) * b2[o];

        const float* e = inp + (b * N + i) * 6;
        float y = e[0], x = e[1], tau = e[2], sig = e[3];
        float* ot = out + (b * N + i) * 6;
        ot[0] = y   + 0.1f * p[0];
        ot[1] = x   + 0.1f * p[1];
        ot[2] = tau + 0.1f * p[2];
        ot[3] = sig + 0.1f * p[3];
        ot[4] = 0.1f * softplus_f(p[4]);
        ot[5] = 0.1f * softplus_f(p[5]);
    }
}

// ---------------------------------------------------------------------------
extern "C" void kernel_launch(void* const* d_in, const int* in_sizes, int n_in,
                              void* d_out, int out_size)
{
    const float* inp = (const float*)d_in[0];
    const float* W1  = (const float*)d_in[1];
    const float* b1  = (const float*)d_in[2];
    const float* W2  = (const float*)d_in[3];
    const float* b2  = (const float*)d_in[4];
    float* out = (float*)d_out;

    k1_build_PQ<<<(B * N * HP + 255) / 256, 256>>>(inp, W1, b1);
    k1b_sumQ<<<B, 512>>>();
    k2_pair_abs_sum<<<B * (N / I_TILE), 256>>>();
    k3_epilogue<<<B * N, 128>>>(inp, W2, b2, out);
}